// round 9
// baseline (speedup 1.0000x reference)
#include <cuda_runtime.h>
#include <stdint.h>

// out[N,32] = segment_sum_e( edge_val[e] * weight[edge_col[e], :] ) into row edge_row[e], + bias
// Inputs (metadata order) — JAX demotes int64->int32 (x64 disabled):
//   d_in[0] = edge_row  int32  [E]
//   d_in[1] = edge_col  int32  [E]
//   d_in[2] = edge_val  f32    [E]
//   d_in[3] = weight    f32    [N*32]
//   d_in[4] = bias      f32    [32]
// d_out = f32 [N*32]
//
// K1: out = bias. K2: spmm.
// Key idea: every gather LDG.128 and every v4 RED is PREDICATED to a single
// 8-lane group, so each memory instruction touches exactly one 128B line.
// This converts expensive within-instruction replay wavefronts (~2.07 cyc)
// into cross-instruction wavefronts (~1.0 cyc) on the saturated L1tex pipe.

static constexpr int D = 32;
static constexpr int ITERS_PER_WARP = 8;   // 4 edges per round
static constexpr int EDGES_PER_WARP = 32;  // lane owns one edge's metadata

// Predicated v4 load: only lanes with pred!=0 execute; w preserved elsewhere ("+f").
__device__ __forceinline__ void pred_ldg_v4(float4& w, const float4* addr, int pred) {
    asm volatile(
        "{\n\t"
        ".reg .pred p;\n\t"
        "setp.ne.u32 p, %4, 0;\n\t"
        "@p ld.global.nc.v4.f32 {%0, %1, %2, %3}, [%5];\n\t"
        "}"
        : "+f"(w.x), "+f"(w.y), "+f"(w.z), "+f"(w.w)
        : "r"(pred), "l"(addr)
        : "memory");
}

// Predicated v4 global reduction.
__device__ __forceinline__ void pred_red_v4(float* addr, float4 v, int pred) {
    asm volatile(
        "{\n\t"
        ".reg .pred p;\n\t"
        "setp.ne.u32 p, %5, 0;\n\t"
        "@p red.global.add.v4.f32 [%0], {%1, %2, %3, %4};\n\t"
        "}"
        :: "l"(addr), "f"(v.x), "f"(v.y), "f"(v.z), "f"(v.w), "r"(pred)
        : "memory");
}

__global__ void init_bias_kernel(float4* __restrict__ out4,
                                 const float4* __restrict__ bias4,
                                 int total4) {
    int i = blockIdx.x * blockDim.x + threadIdx.x;
    if (i < total4) {
        out4[i] = bias4[i & 7];            // 32 floats = 8 float4
    }
}

__global__ __launch_bounds__(256)
void spmm_coo_pred_kernel(const int*    __restrict__ edge_row,
                          const int*    __restrict__ edge_col,
                          const float*  __restrict__ edge_val,
                          const float4* __restrict__ weight4, // [N*8]
                          float*        __restrict__ out,
                          int E) {
    int gtid    = blockIdx.x * blockDim.x + threadIdx.x;
    int warp_id = gtid >> 5;
    int lane    = gtid & 31;
    int sub     = lane >> 3;               // 8-lane group id (0..3)
    int feat4   = lane & 7;                // float4 chunk of the 32 features

    // Lane-owned edge metadata: 3 fully-coalesced 128B loads per warp.
    int e_lane = warp_id * EDGES_PER_WARP + lane;
    int   r_own, c_own;
    float v_own;
    if (e_lane < E) {
        r_own = edge_row[e_lane];
        c_own = edge_col[e_lane];
        v_own = edge_val[e_lane];
    } else {
        r_own = 0; c_own = 0; v_own = 0.0f;  // RED of 0.0 -> exact no-op
    }

#pragma unroll
    for (int it = 0; it < ITERS_PER_WARP; ++it) {
        int src = it * 4 + sub;             // this group's edge for this round
        int   r = __shfl_sync(0xffffffffu, r_own, src);
        int   c = __shfl_sync(0xffffffffu, c_own, src);
        float v = __shfl_sync(0xffffffffu, v_own, src);

        const float4* gaddr = &weight4[(size_t)c * 8 + feat4];
        float*        oaddr = &out[(size_t)r * D + feat4 * 4];

        float4 w = make_float4(0.f, 0.f, 0.f, 0.f);
        // One instruction per 8-lane group => one 128B line per LDG.
        pred_ldg_v4(w, gaddr, sub == 0);
        pred_ldg_v4(w, gaddr, sub == 1);
        pred_ldg_v4(w, gaddr, sub == 2);
        pred_ldg_v4(w, gaddr, sub == 3);

        float4 contrib = make_float4(v * w.x, v * w.y, v * w.z, v * w.w);

        // One instruction per 8-lane group => one 128B line per RED.
        pred_red_v4(oaddr, contrib, sub == 0);
        pred_red_v4(oaddr, contrib, sub == 1);
        pred_red_v4(oaddr, contrib, sub == 2);
        pred_red_v4(oaddr, contrib, sub == 3);
    }
}

extern "C" void kernel_launch(void* const* d_in, const int* in_sizes, int n_in,
                              void* d_out, int out_size) {
    const int*    edge_row = (const int*)d_in[0];
    const int*    edge_col = (const int*)d_in[1];
    const float*  edge_val = (const float*)d_in[2];
    const float4* weight4  = (const float4*)d_in[3];
    const float4* bias4    = (const float4*)d_in[4];
    float*        out      = (float*)d_out;

    const int E      = in_sizes[2];        // edge count
    const int total4 = out_size / 4;       // N * 8

    {
        int threads = 256;
        int blocks  = (total4 + threads - 1) / threads;
        init_bias_kernel<<<blocks, threads>>>((float4*)out, bias4, total4);
    }
    {
        int warps   = (E + EDGES_PER_WARP - 1) / EDGES_PER_WARP;
        int threads = 256;                 // 8 warps/block
        int blocks  = (warps + 7) / 8;
        spmm_coo_pred_kernel<<<blocks, threads>>>(edge_row, edge_col, edge_val,
                                                  weight4, out, E);
    }
}

// round 10
// speedup vs baseline: 1.3519x; 1.3519x over previous
#include <cuda_runtime.h>
#include <stdint.h>

// out[N,32] = segment_sum_e( edge_val[e] * weight[edge_col[e], :] ) into row edge_row[e], + bias
// Inputs (metadata order) — JAX demotes int64->int32 (x64 disabled):
//   d_in[0] = edge_row  int32  [E]
//   d_in[1] = edge_col  int32  [E]
//   d_in[2] = edge_val  f32    [E]
//   d_in[3] = weight    f32    [N*32]
//   d_in[4] = bias      f32    [32]
// d_out = f32 [N*32]
//
// R8 structure (best so far): lane-owned edge metadata redistributed via SHFL,
// 8 lanes/edge, warp-wide LDG.128 gathers + v4 f32 REDs.
// This round: kill L1 allocation on the one-shot traffic —
//   gathers:  ld.global.cg (L2-only; weight hit rate in L1 is ~2%, fills are waste)
//   indices:  ld.global.cs (streaming, evict-first)
// REDs already bypass L1 allocation.

static constexpr int D = 32;
static constexpr int ITERS_PER_WARP = 8;   // 4 edges per round
static constexpr int EDGES_PER_WARP = 32;  // lane owns one edge's metadata

__device__ __forceinline__ void red_add_v4(float* addr, float4 v) {
    asm volatile("red.global.add.v4.f32 [%0], {%1, %2, %3, %4};"
                 :: "l"(addr), "f"(v.x), "f"(v.y), "f"(v.z), "f"(v.w)
                 : "memory");
}

// L2-only vector load: no L1 line allocation/fill for never-reused gathers.
__device__ __forceinline__ float4 ldg_cg_v4(const float4* addr) {
    float4 w;
    asm volatile("ld.global.cg.v4.f32 {%0, %1, %2, %3}, [%4];"
                 : "=f"(w.x), "=f"(w.y), "=f"(w.z), "=f"(w.w)
                 : "l"(addr));
    return w;
}

__global__ void init_bias_kernel(float4* __restrict__ out4,
                                 const float4* __restrict__ bias4,
                                 int total4) {
    int i = blockIdx.x * blockDim.x + threadIdx.x;
    if (i < total4) {
        out4[i] = bias4[i & 7];            // 32 floats = 8 float4
    }
}

__global__ __launch_bounds__(256)
void spmm_coo_cg_kernel(const int*    __restrict__ edge_row,
                        const int*    __restrict__ edge_col,
                        const float*  __restrict__ edge_val,
                        const float4* __restrict__ weight4, // [N*8]
                        float*        __restrict__ out,
                        int E) {
    int gtid    = blockIdx.x * blockDim.x + threadIdx.x;
    int warp_id = gtid >> 5;
    int lane    = gtid & 31;
    int sub     = lane >> 3;               // edge within group of 4
    int feat4   = lane & 7;                // float4 chunk of the 32 features

    // Lane-owned edge metadata: 3 fully-coalesced streaming loads per warp.
    int e_lane = warp_id * EDGES_PER_WARP + lane;
    int   r_own, c_own;
    float v_own;
    if (e_lane < E) {
        r_own = __ldcs(&edge_row[e_lane]);
        c_own = __ldcs(&edge_col[e_lane]);
        v_own = __ldcs(&edge_val[e_lane]);
    } else {
        r_own = 0; c_own = 0; v_own = 0.0f;  // RED of 0.0 -> exact no-op
    }

#pragma unroll
    for (int it = 0; it < ITERS_PER_WARP; ++it) {
        int src = it * 4 + sub;             // lane holding this edge's triple
        int   r = __shfl_sync(0xffffffffu, r_own, src);
        int   c = __shfl_sync(0xffffffffu, c_own, src);
        float v = __shfl_sync(0xffffffffu, v_own, src);

        float4 w = ldg_cg_v4(&weight4[(size_t)c * 8 + feat4]);   // LDG.128 .cg
        float4 contrib = make_float4(v * w.x, v * w.y, v * w.z, v * w.w);
        red_add_v4(&out[(size_t)r * D + feat4 * 4], contrib);
    }
}

extern "C" void kernel_launch(void* const* d_in, const int* in_sizes, int n_in,
                              void* d_out, int out_size) {
    const int*    edge_row = (const int*)d_in[0];
    const int*    edge_col = (const int*)d_in[1];
    const float*  edge_val = (const float*)d_in[2];
    const float4* weight4  = (const float4*)d_in[3];
    const float4* bias4    = (const float4*)d_in[4];
    float*        out      = (float*)d_out;

    const int E      = in_sizes[2];        // edge count
    const int total4 = out_size / 4;       // N * 8

    {
        int threads = 256;
        int blocks  = (total4 + threads - 1) / threads;
        init_bias_kernel<<<blocks, threads>>>((float4*)out, bias4, total4);
    }
    {
        int warps   = (E + EDGES_PER_WARP - 1) / EDGES_PER_WARP;
        int threads = 256;                 // 8 warps/block
        int blocks  = (warps + 7) / 8;
        spmm_coo_cg_kernel<<<blocks, threads>>>(edge_row, edge_col, edge_val,
                                                weight4, out, E);
    }
}

// round 11
// speedup vs baseline: 1.6718x; 1.2366x over previous
#include <cuda_runtime.h>
#include <cuda_fp16.h>
#include <stdint.h>

// out[N,32] = segment_sum_e( edge_val[e] * weight[edge_col[e], :] ) into row edge_row[e], + bias
// Inputs (metadata order) — JAX demotes int64->int32 (x64 disabled):
//   d_in[0] = edge_row  int32  [E]
//   d_in[1] = edge_col  int32  [E]
//   d_in[2] = edge_val  f32    [E]
//   d_in[3] = weight    f32    [N*32]
//   d_in[4] = bias      f32    [32]
// d_out = f32 [N*32]
//
// Empirical law (R2..R10): spmm time ≈ 2.9ns x atomic lane-requests; nothing
// else matters. So: accumulate into an fp16 scratch buffer with v4.f16x2
// REDs — 4 requests/edge instead of 8 — then finalize out = f32(acc) + bias.
//  K1: zero fp16 accumulator (6.4MB)
//  K2: spmm — 4 lanes/edge, f32 gathers + math, one convert, v4.f16x2 RED
//  K3: finalize — out = float(acc) + bias

static constexpr int D       = 32;
static constexpr int N_NODES = 100000;
static constexpr int ITERS_PER_WARP = 4;   // 8 edges per round
static constexpr int EDGES_PER_WARP = 32;  // lane owns one edge's metadata

// fp16 accumulator: 32 halves (=16 half2, 64B) per row.
__device__ __half2 g_acc[(size_t)N_NODES * (D / 2)];

// 16B fp16x2 global reduction (sm_90+): 8 half adds per request.
__device__ __forceinline__ void red_add_v4_f16x2(void* addr, uint32_t p0,
                                                 uint32_t p1, uint32_t p2,
                                                 uint32_t p3) {
    asm volatile("red.global.add.noftz.v4.f16x2 [%0], {%1, %2, %3, %4};"
                 :: "l"(addr), "r"(p0), "r"(p1), "r"(p2), "r"(p3)
                 : "memory");
}

__device__ __forceinline__ uint32_t cvt_h2(float a, float b) {
    __half2 h = __floats2half2_rn(a, b);   // low=a, high=b
    return *reinterpret_cast<const uint32_t*>(&h);
}

// ---------------- K1: zero the accumulator ----------------
__global__ void zero_acc_kernel(int n16) {          // n16 = bytes/16
    int i = blockIdx.x * blockDim.x + threadIdx.x;
    if (i < n16) {
        reinterpret_cast<uint4*>(g_acc)[i] = make_uint4(0, 0, 0, 0);
    }
}

// ---------------- K2: spmm ----------------
// 4 lanes per edge: lane sub=lane>>2 picks the edge of this round, f=lane&3
// picks a 16B chunk (8 features). Gathers: 2x LDG.128 f32 per lane (loads are
// not binding). One rounding at the f16x2 convert, then a single 16B RED.
__global__ __launch_bounds__(256)
void spmm_coo_h2_kernel(const int*    __restrict__ edge_row,
                        const int*    __restrict__ edge_col,
                        const float*  __restrict__ edge_val,
                        const float4* __restrict__ weight4, // [N*8]
                        int E) {
    int gtid    = blockIdx.x * blockDim.x + threadIdx.x;
    int warp_id = gtid >> 5;
    int lane    = gtid & 31;
    int sub     = lane >> 2;               // 0..7: edge within round
    int f       = lane & 3;                // 0..3: 16B chunk (8 features)

    // Lane-owned edge metadata: 3 fully-coalesced loads per warp.
    int e_lane = warp_id * EDGES_PER_WARP + lane;
    int   r_own, c_own;
    float v_own;
    if (e_lane < E) {
        r_own = edge_row[e_lane];
        c_own = edge_col[e_lane];
        v_own = edge_val[e_lane];
    } else {
        r_own = 0; c_own = 0; v_own = 0.0f;  // +0 contributions: exact no-op
    }

#pragma unroll
    for (int it = 0; it < ITERS_PER_WARP; ++it) {
        int src = it * 8 + sub;             // lane holding this edge's triple
        int   r = __shfl_sync(0xffffffffu, r_own, src);
        int   c = __shfl_sync(0xffffffffu, c_own, src);
        float v = __shfl_sync(0xffffffffu, v_own, src);

        // 8 features per lane: two float4 loads.
        const float4* wbase = &weight4[(size_t)c * 8 + f * 2];
        float4 wa = __ldg(&wbase[0]);
        float4 wb = __ldg(&wbase[1]);

        uint32_t p0 = cvt_h2(v * wa.x, v * wa.y);
        uint32_t p1 = cvt_h2(v * wa.z, v * wa.w);
        uint32_t p2 = cvt_h2(v * wb.x, v * wb.y);
        uint32_t p3 = cvt_h2(v * wb.z, v * wb.w);

        // One 16B atomic request per lane, 4 per edge.
        char* addr = reinterpret_cast<char*>(g_acc) + (size_t)r * 64 + f * 16;
        red_add_v4_f16x2(addr, p0, p1, p2, p3);
    }
}

// ---------------- K3: finalize out = float(acc) + bias ----------------
__global__ void finalize_kernel(float4* __restrict__ out4,
                                const float4* __restrict__ bias4,
                                int total4) {                 // total4 = N*8
    int i = blockIdx.x * blockDim.x + threadIdx.x;
    if (i < total4) {
        // 4 output floats = 2 half2 from the accumulator.
        __half2 a = g_acc[(size_t)i * 2 + 0];
        __half2 b = g_acc[(size_t)i * 2 + 1];
        float2 fa = __half22float2(a);
        float2 fb = __half22float2(b);
        float4 bias = bias4[i & 7];
        out4[i] = make_float4(fa.x + bias.x, fa.y + bias.y,
                              fb.x + bias.z, fb.y + bias.w);
    }
}

extern "C" void kernel_launch(void* const* d_in, const int* in_sizes, int n_in,
                              void* d_out, int out_size) {
    const int*    edge_row = (const int*)d_in[0];
    const int*    edge_col = (const int*)d_in[1];
    const float*  edge_val = (const float*)d_in[2];
    const float4* weight4  = (const float4*)d_in[3];
    const float4* bias4    = (const float4*)d_in[4];
    float*        out      = (float*)d_out;

    const int E      = in_sizes[2];              // edge count
    const int N      = out_size / D;
    const int total4 = out_size / 4;             // N*8
    const int acc16  = N * D * 2 / 16;           // accumulator bytes / 16

    {
        int threads = 256;
        int blocks  = (acc16 + threads - 1) / threads;
        zero_acc_kernel<<<blocks, threads>>>(acc16);
    }
    {
        int warps   = (E + EDGES_PER_WARP - 1) / EDGES_PER_WARP;
        int threads = 256;                       // 8 warps/block
        int blocks  = (warps + 7) / 8;
        spmm_coo_h2_kernel<<<blocks, threads>>>(edge_row, edge_col, edge_val,
                                                weight4, E);
    }
    {
        int threads = 256;
        int blocks  = (total4 + threads - 1) / threads;
        finalize_kernel<<<blocks, threads>>>((float4*)out, bias4, total4);
    }
}